// round 3
// baseline (speedup 1.0000x reference)
#include <cuda_runtime.h>
#include <cstdint>

#define NMAX   500000
#define HBITS  21
#define HSIZE  (1u << HBITS)
#define HMASK  (HSIZE - 1u)
#define EMPTYK 0xFFFFFFFFu
#define TPB5   192
#define NPT    4

// ---------------- device scratch (static globals: allowed scratch path) ----------------
__device__ uint32_t g_keys[HSIZE];
__device__ int      g_vals[HSIZE];
__device__ int      g_counter;
__device__ int      g_pt2vox[NMAX];
__device__ float    g_sums[3][NMAX * 64];   // per-scale compact voxel feature sums
__device__ int      g_counts[3][NMAX];      // per-scale voxel point counts
__device__ int      g_ptidx[3][NMAX];       // per-scale chosen corner voxel id per point

__device__ __forceinline__ uint32_t hash32(uint32_t x) {
    x ^= x >> 16; x *= 0x85ebca6bu;
    x ^= x >> 13; x *= 0xc2b2ae35u;
    x ^= x >> 16;
    return x;
}

__device__ __forceinline__ unsigned long long fma2(unsigned long long a,
                                                   unsigned long long b,
                                                   unsigned long long c) {
    unsigned long long d;
    asm("fma.rn.f32x2 %0, %1, %2, %3;" : "=l"(d) : "l"(a), "l"(b), "l"(c));
    return d;
}

__device__ __forceinline__ float2 unpack2(unsigned long long v) {
    float2 r;
    asm("mov.b64 {%0, %1}, %2;" : "=f"(r.x), "=f"(r.y) : "l"(v));
    return r;
}

__device__ __forceinline__ unsigned long long pack2(float lo, float hi) {
    unsigned long long r;
    asm("mov.b64 %0, {%1, %2};" : "=l"(r) : "f"(lo), "f"(hi));
    return r;
}

// ---------------- K1: clear hash + per-scale sums/counts ----------------
__global__ void k_clear(int si, int n) {
    int tid = blockIdx.x * blockDim.x + threadIdx.x;
    int stride = gridDim.x * blockDim.x;
    int m4 = n * 16;  // float4 chunks of sums
    float4 z = make_float4(0.f, 0.f, 0.f, 0.f);
    float4* s4 = reinterpret_cast<float4*>(&g_sums[si][0]);
    for (int i = tid; i < m4; i += stride) s4[i] = z;
    for (int i = tid; i < (int)HSIZE; i += stride) { g_keys[i] = EMPTYK; g_vals[i] = -1; }
    for (int i = tid; i < n; i += stride) g_counts[si][i] = 0;
    if (tid == 0) g_counter = 0;
}

// ---------------- K2: hash-insert voxel keys, assign compact ids, count points ----------------
__global__ void k_insert(const int* __restrict__ coords, int n, int shift, int si) {
    int i = blockIdx.x * blockDim.x + threadIdx.x;
    if (i >= n) return;
    int4 cd = reinterpret_cast<const int4*>(coords)[i];
    int vx = cd.x >> shift, vy = cd.y >> shift, vz = cd.z >> shift;
    uint32_t key = (uint32_t)((((cd.w * 512) + vx) * 512 + vy) * 512 + vz);
    uint32_t slot = hash32(key) & HMASK;
    int id = -1;
#pragma unroll 1
    while (true) {
        uint32_t old = atomicCAS(&g_keys[slot], EMPTYK, key);
        if (old == EMPTYK) {
            id = atomicAdd(&g_counter, 1);
            atomicExch(&g_vals[slot], id);
            break;
        }
        if (old == key) {
            volatile int* vp = (volatile int*)&g_vals[slot];
#pragma unroll 1
            while ((id = *vp) < 0) { __nanosleep(40); }
            break;
        }
        slot = (slot + 1) & HMASK;
    }
    g_pt2vox[i] = id;
    atomicAdd(&g_counts[si][id], 1);
}

// ---------------- K3: accumulate per-voxel feature sums (vector red) ----------------
__global__ void k_accum(const float* __restrict__ feats, int si, int n) {
    int tid = blockIdx.x * blockDim.x + threadIdx.x;
    if (tid >= n * 16) return;
    int p = tid >> 4, q = tid & 15;
    float4 v = reinterpret_cast<const float4*>(feats)[tid];
    int vid = g_pt2vox[p];
    float* dst = &g_sums[si][(size_t)vid * 64 + q * 4];
    asm volatile("red.global.add.v4.f32 [%0], {%1, %2, %3, %4};"
                 :: "l"(dst), "f"(v.x), "f"(v.y), "f"(v.z), "f"(v.w)
                 : "memory");
}

// ---------------- K4: 8-corner probe, exact trilinear argmax, select voxel id ----------------
__device__ __forceinline__ int hlookup(uint32_t key) {
    uint32_t slot = hash32(key) & HMASK;
#pragma unroll 1
    while (true) {
        uint32_t k = g_keys[slot];
        if (k == key) return g_vals[slot];
        if (k == EMPTYK) return -1;
        slot = (slot + 1) & HMASK;
    }
}

__global__ void k_select(const int* __restrict__ coords, int n, int shift, int si) {
    int i = blockIdx.x * blockDim.x + threadIdx.x;
    if (i >= n) return;
    int4 cd = reinterpret_cast<const int4*>(coords)[i];
    int scale = 1 << shift;
    float invs = 1.0f / (float)scale;
    int vx = cd.x >> shift, vy = cd.y >> shift, vz = cd.z >> shift;
    float fx = (float)(cd.x - (vx << shift)) * invs;   // exact binary fractions
    float fy = (float)(cd.y - (vy << shift)) * invs;
    float fz = (float)(cd.z - (vz << shift)) * invs;
    float gx = 1.0f - fx, gy = 1.0f - fy, gz = 1.0f - fz;

    float bestw = -1.0f;
    int bestid = 0;
#pragma unroll
    for (int j = 0; j < 8; j++) {
        int bx = (j >> 2) & 1, by = (j >> 1) & 1, bz = j & 1;
        float w = (bx ? fx : gx) * (by ? fy : gy) * (bz ? fz : gz);  // exact
        uint32_t key = (uint32_t)((((cd.w * 512) + (vx + bx)) * 512 + (vy + by)) * 512 + (vz + bz));
        int id = hlookup(key);
        float val = (id >= 0) ? w : 0.0f;
        if (val > bestw) { bestw = val; bestid = id; }   // first-max == jnp.argmax
    }
    g_ptidx[si][i] = bestid;
}

// ---------------- K5: fused 3-scale residual MLP + attention ----------------
// 192 threads: thread t -> (s = t/64, c = t%64). W1/W2 column of (s,c) held in
// registers packed as f32x2 pairs. res/h vectors broadcast from smem.
__global__ __launch_bounds__(TPB5, 2) void k_fuse(
    const float* __restrict__ feats,
    const float* __restrict__ W1g, const float* __restrict__ b1g,
    const float* __restrict__ W2g, const float* __restrict__ b2g,
    const float* __restrict__ Wag, const float* __restrict__ bag,
    float* __restrict__ out, int n)
{
    extern __shared__ float sm[];
    const int t = threadIdx.x;
    const int s = t >> 6;
    const int c = t & 63;
    const int warp = t >> 5;
    const int lane = t & 31;

    // ---- stage weights through smem, pack columns into registers ----
    unsigned long long w1p[32], w2p[32];
    for (int i = t; i < 3 * 64 * 64; i += TPB5) sm[i] = W1g[i];
    __syncthreads();
#pragma unroll
    for (int k2 = 0; k2 < 32; k2++)
        w1p[k2] = pack2(sm[s * 4096 + (2 * k2) * 64 + c], sm[s * 4096 + (2 * k2 + 1) * 64 + c]);
    __syncthreads();
    for (int i = t; i < 3 * 64 * 64; i += TPB5) sm[i] = W2g[i];
    __syncthreads();
#pragma unroll
    for (int k2 = 0; k2 < 32; k2++)
        w2p[k2] = pack2(sm[s * 4096 + (2 * k2) * 64 + c], sm[s * 4096 + (2 * k2 + 1) * 64 + c]);
    __syncthreads();

    const float b1r = b1g[s * 64 + c];
    const float b2r = b2g[s * 64 + c];
    const float war = Wag[s * 64 + c];

    // working smem (overlaps the staging region; staging is done)
    float* pf    = sm;                    // [NPT][64]
    float* resb  = sm + NPT * 64;         // [NPT][3][64]
    float* hbb   = resb + NPT * 192;      // [NPT][3][64]
    float* msbb  = hbb + NPT * 192;       // [NPT][3][64]
    float* wpart = msbb + NPT * 192;      // [NPT][8]
    float* attv  = wpart + NPT * 8;       // [NPT][4]

    for (int i0 = blockIdx.x * NPT; i0 < n; i0 += gridDim.x * NPT) {
        int np = (n - i0 < NPT) ? (n - i0) : NPT;

        if (t < 64)
            for (int p = 0; p < np; p++)
                pf[p * 64 + t] = feats[(size_t)(i0 + p) * 64 + t];

        float up[NPT];
#pragma unroll
        for (int p = 0; p < NPT; p++) {
            if (p < np) {
                int idx = g_ptidx[s][i0 + p];
                float inv = 1.0f / (float)g_counts[s][idx];
                up[p] = g_sums[s][(size_t)idx * 64 + c] * inv;
            }
        }
        __syncthreads();  // S1: pf ready

        for (int p = 0; p < np; p++)
            resb[(p * 3 + s) * 64 + c] = pf[p * 64 + c] - up[p];
        __syncthreads();  // S2: res ready

        // GEMV1: h = relu(res @ W1 + b1) * feats
        {
            unsigned long long acc[NPT];
#pragma unroll
            for (int p = 0; p < NPT; p++) acc[p] = 0ull;
#pragma unroll
            for (int k4 = 0; k4 < 16; k4++) {
#pragma unroll
                for (int p = 0; p < NPT; p++) {
                    if (p < np) {
                        ulonglong2 rv = *reinterpret_cast<const ulonglong2*>(
                            &resb[(p * 3 + s) * 64 + k4 * 4]);
                        acc[p] = fma2(rv.x, w1p[2 * k4], acc[p]);
                        acc[p] = fma2(rv.y, w1p[2 * k4 + 1], acc[p]);
                    }
                }
            }
            for (int p = 0; p < np; p++) {
                float2 u = unpack2(acc[p]);
                float h = u.x + u.y + b1r;
                hbb[(p * 3 + s) * 64 + c] = fmaxf(h, 0.0f) * pf[p * 64 + c];
            }
        }
        __syncthreads();  // S3: h ready

        // GEMV2: ms = relu(h @ W2 + b2)
        {
            unsigned long long acc[NPT];
#pragma unroll
            for (int p = 0; p < NPT; p++) acc[p] = 0ull;
#pragma unroll
            for (int k4 = 0; k4 < 16; k4++) {
#pragma unroll
                for (int p = 0; p < NPT; p++) {
                    if (p < np) {
                        ulonglong2 rv = *reinterpret_cast<const ulonglong2*>(
                            &hbb[(p * 3 + s) * 64 + k4 * 4]);
                        acc[p] = fma2(rv.x, w2p[2 * k4], acc[p]);
                        acc[p] = fma2(rv.y, w2p[2 * k4 + 1], acc[p]);
                    }
                }
            }
            for (int p = 0; p < np; p++) {
                float2 u = unpack2(acc[p]);
                msbb[(p * 3 + s) * 64 + c] = fmaxf(u.x + u.y + b2r, 0.0f);
            }
        }
        __syncthreads();  // S4: ms ready

        // attention logits: per warp partial dot(ssum, Wa[s])
#pragma unroll
        for (int p = 0; p < NPT; p++) {
            if (p < np) {
                float ss = msbb[(p * 3 + 0) * 64 + c] + msbb[(p * 3 + 1) * 64 + c]
                         + msbb[(p * 3 + 2) * 64 + c];
                float pa = ss * war;
                pa += __shfl_xor_sync(0xffffffffu, pa, 16);
                pa += __shfl_xor_sync(0xffffffffu, pa, 8);
                pa += __shfl_xor_sync(0xffffffffu, pa, 4);
                pa += __shfl_xor_sync(0xffffffffu, pa, 2);
                pa += __shfl_xor_sync(0xffffffffu, pa, 1);
                if (lane == 0) wpart[p * 8 + warp] = pa;
            }
        }
        __syncthreads();  // S5

        if (t < 3 * np) {
            int p = t / 3, s2 = t % 3;
            float x = wpart[p * 8 + 2 * s2] + wpart[p * 8 + 2 * s2 + 1] + bag[s2];
            attv[p * 4 + s2] = 1.0f / (1.0f + expf(-x));
        }
        __syncthreads();  // S6

        if (t < 64) {
            for (int p = 0; p < np; p++) {
                float o = msbb[(p * 3 + 0) * 64 + t] * attv[p * 4 + 0]
                        + msbb[(p * 3 + 1) * 64 + t] * attv[p * 4 + 1]
                        + msbb[(p * 3 + 2) * 64 + t] * attv[p * 4 + 2];
                out[(size_t)(i0 + p) * 64 + t] = o;
            }
        }
        // no trailing sync needed: next-iter smem writes are all behind S1..S5
    }
}

// ---------------- host launcher ----------------
extern "C" void kernel_launch(void* const* d_in, const int* in_sizes, int n_in,
                              void* d_out, int out_size) {
    const float* feats = (const float*)d_in[0];
    const int*   coords = (const int*)d_in[1];
    const float* W1 = (const float*)d_in[2];
    const float* b1 = (const float*)d_in[3];
    const float* W2 = (const float*)d_in[4];
    const float* b2 = (const float*)d_in[5];
    const float* Wa = (const float*)d_in[6];
    const float* ba = (const float*)d_in[7];
    float* out = (float*)d_out;

    int n = in_sizes[1] / 4;     // coords is (N,4) int32
    if (n > NMAX) n = NMAX;

    for (int si = 0; si < 3; si++) {
        int shift = si + 1;      // scales 2, 4, 8
        k_clear<<<4096, 256>>>(si, n);
        k_insert<<<(n + 255) / 256, 256>>>(coords, n, shift, si);
        k_accum<<<(n * 16 + 255) / 256, 256>>>(feats, si, n);
        k_select<<<(n + 255) / 256, 256>>>(coords, n, shift, si);
    }

    cudaFuncSetAttribute(k_fuse, cudaFuncAttributeMaxDynamicSharedMemorySize, 49152);
    k_fuse<<<592, TPB5, 49152>>>(feats, W1, b1, W2, b2, Wa, ba, out, n);
}

// round 4
// speedup vs baseline: 1.6110x; 1.6110x over previous
#include <cuda_runtime.h>
#include <cstdint>

#define NMAX   500000
#define HBITS  21
#define HSIZE  (1u << HBITS)
#define HMASK  (HSIZE - 1u)
#define EMPTYK 0xFFFFFFFFu
#define TPB5   384

typedef unsigned long long ull;

// ---------------- device scratch ----------------
__device__ uint32_t g_keys[3][HSIZE];
__device__ int      g_vals[3][HSIZE];
__device__ int      g_counter[3];
__device__ int      g_pt2vox[3][NMAX];
__device__ float    g_sums[3][NMAX * 64];
__device__ int      g_counts[3][NMAX];
__device__ int      g_ptidx[3][NMAX];

__device__ __forceinline__ uint32_t hash32(uint32_t x) {
    x ^= x >> 16; x *= 0x85ebca6bu;
    x ^= x >> 13; x *= 0xc2b2ae35u;
    x ^= x >> 16;
    return x;
}

__device__ __forceinline__ ull fma2(ull a, ull b, ull c) {
    ull d;
    asm("fma.rn.f32x2 %0, %1, %2, %3;" : "=l"(d) : "l"(a), "l"(b), "l"(c));
    return d;
}
__device__ __forceinline__ float2 unpack2(ull v) {
    float2 r;
    asm("mov.b64 {%0, %1}, %2;" : "=f"(r.x), "=f"(r.y) : "l"(v));
    return r;
}

// ---------------- K1: clear all 3 hash tables + sums/counts ----------------
__global__ void k_clear(int n) {
    int tid = blockIdx.x * blockDim.x + threadIdx.x;
    int stride = gridDim.x * blockDim.x;
    int m4 = n * 16;
    float4 z = make_float4(0.f, 0.f, 0.f, 0.f);
#pragma unroll
    for (int s = 0; s < 3; s++) {
        float4* s4 = reinterpret_cast<float4*>(&g_sums[s][0]);
        for (int i = tid; i < m4; i += stride) s4[i] = z;
    }
    for (int i = tid; i < (int)HSIZE; i += stride) {
        g_keys[0][i] = EMPTYK; g_keys[1][i] = EMPTYK; g_keys[2][i] = EMPTYK;
        g_vals[0][i] = -1;     g_vals[1][i] = -1;     g_vals[2][i] = -1;
    }
    for (int i = tid; i < n; i += stride) {
        g_counts[0][i] = 0; g_counts[1][i] = 0; g_counts[2][i] = 0;
    }
    if (tid == 0) { g_counter[0] = 0; g_counter[1] = 0; g_counter[2] = 0; }
}

// ---------------- K2: hash-insert (all scales via blockIdx.y) ----------------
__global__ void k_insert(const int* __restrict__ coords, int n) {
    int i = blockIdx.x * blockDim.x + threadIdx.x;
    if (i >= n) return;
    int si = blockIdx.y;
    int shift = si + 1;
    int4 cd = reinterpret_cast<const int4*>(coords)[i];
    int vx = cd.x >> shift, vy = cd.y >> shift, vz = cd.z >> shift;
    uint32_t key = (uint32_t)((((cd.w * 512) + vx) * 512 + vy) * 512 + vz);
    uint32_t slot = hash32(key) & HMASK;
    int id = -1;
#pragma unroll 1
    while (true) {
        uint32_t old = atomicCAS(&g_keys[si][slot], EMPTYK, key);
        if (old == EMPTYK) {
            id = atomicAdd(&g_counter[si], 1);
            atomicExch(&g_vals[si][slot], id);
            break;
        }
        if (old == key) {
            volatile int* vp = (volatile int*)&g_vals[si][slot];
#pragma unroll 1
            while ((id = *vp) < 0) { __nanosleep(40); }
            break;
        }
        slot = (slot + 1) & HMASK;
    }
    g_pt2vox[si][i] = id;
    atomicAdd(&g_counts[si][id], 1);
}

// ---------------- K3: per-voxel feature sums ----------------
__global__ void k_accum(const float* __restrict__ feats, int n) {
    int tid = blockIdx.x * blockDim.x + threadIdx.x;
    if (tid >= n * 16) return;
    int si = blockIdx.y;
    int p = tid >> 4, q = tid & 15;
    float4 v = reinterpret_cast<const float4*>(feats)[tid];
    int vid = g_pt2vox[si][p];
    float* dst = &g_sums[si][(size_t)vid * 64 + q * 4];
    asm volatile("red.global.add.v4.f32 [%0], {%1, %2, %3, %4};"
                 :: "l"(dst), "f"(v.x), "f"(v.y), "f"(v.z), "f"(v.w)
                 : "memory");
}

// ---------------- K4: 8-corner probe + exact trilinear argmax ----------------
__device__ __forceinline__ int hlookup(int si, uint32_t key) {
    uint32_t slot = hash32(key) & HMASK;
#pragma unroll 1
    while (true) {
        uint32_t k = g_keys[si][slot];
        if (k == key) return g_vals[si][slot];
        if (k == EMPTYK) return -1;
        slot = (slot + 1) & HMASK;
    }
}

__global__ void k_select(const int* __restrict__ coords, int n) {
    int i = blockIdx.x * blockDim.x + threadIdx.x;
    if (i >= n) return;
    int si = blockIdx.y;
    int shift = si + 1;
    int4 cd = reinterpret_cast<const int4*>(coords)[i];
    int scale = 1 << shift;
    float invs = 1.0f / (float)scale;
    int vx = cd.x >> shift, vy = cd.y >> shift, vz = cd.z >> shift;
    float fx = (float)(cd.x - (vx << shift)) * invs;   // exact binary fractions
    float fy = (float)(cd.y - (vy << shift)) * invs;
    float fz = (float)(cd.z - (vz << shift)) * invs;
    float gx = 1.0f - fx, gy = 1.0f - fy, gz = 1.0f - fz;

    float bestw = -1.0f;
    int bestid = 0;
#pragma unroll
    for (int j = 0; j < 8; j++) {
        int bx = (j >> 2) & 1, by = (j >> 1) & 1, bz = j & 1;
        float w = (bx ? fx : gx) * (by ? fy : gy) * (bz ? fz : gz);  // exact
        uint32_t key = (uint32_t)((((cd.w * 512) + (vx + bx)) * 512 + (vy + by)) * 512 + (vz + bz));
        int id = hlookup(si, key);
        float val = (id >= 0) ? w : 0.0f;
        if (val > bestw) { bestw = val; bestid = id; }  // first-max == jnp.argmax
    }
    g_ptidx[si][i] = bestid;
}

// ---------------- K5: fused 3-scale residual MLP + attention ----------------
// 384 threads: t -> (s = t/128, g = (t%128)/32, cp = t%32).
// Thread owns channels {2cp, 2cp+1} for 8 points of group g, scale s.
// Weights (all 3 scales, W1+W2, natural [k][c] layout) persist in smem.
// Activations stored DUPLICATED (v,v) so the f32x2 broadcast operand is a
// single LDS — no repack ALU. res/h buffers are warp-private (syncwarp only).
#define OFF_W     0          // 24576 floats (96KB): [s][layer][k][c]
#define OFF_RES   24576      // [3][32][128] dup    (48KB)
#define OFF_H     36864      // [3][32][128] dup    (48KB)
#define OFF_MS    49152      // [3][32][64]         (24KB)
#define OFF_ATT   55296      // [3][32]
#define SMEM_FLTS 55392
#define SMEM_BYTES (SMEM_FLTS * 4)

__global__ __launch_bounds__(TPB5, 1) void k_fuse(
    const float* __restrict__ feats,
    const float* __restrict__ W1g, const float* __restrict__ b1g,
    const float* __restrict__ W2g, const float* __restrict__ b2g,
    const float* __restrict__ Wag, const float* __restrict__ bag,
    float* __restrict__ out, int n)
{
    extern __shared__ float sm[];
    const int t  = threadIdx.x;
    const int s  = t >> 7;
    const int g  = (t & 127) >> 5;
    const int cp = t & 31;
    const int c0 = 2 * cp;

    // ---- stage all weights into smem ([s][layer][k][c], layer-interleaved) ----
    {
        const float4* W14 = (const float4*)W1g;
        const float4* W24 = (const float4*)W2g;
        float4* smW4 = (float4*)sm;
        for (int j = t; j < 3072; j += TPB5) {
            int ss = j >> 10;                  // scale of this chunk
            smW4[j + ss * 1024]        = W14[j];   // layer 0
            smW4[j + ss * 1024 + 1024] = W24[j];   // layer 1
        }
    }
    const float b1c0 = b1g[s * 64 + c0], b1c1 = b1g[s * 64 + c0 + 1];
    const float b2c0 = b2g[s * 64 + c0], b2c1 = b2g[s * 64 + c0 + 1];
    const float wac0 = Wag[s * 64 + c0], wac1 = Wag[s * 64 + c0 + 1];
    const float bas  = bag[s];
    __syncthreads();

    const float* w1base = sm + OFF_W + (s * 2 + 0) * 4096 + c0;
    const float* w2base = sm + OFF_W + (s * 2 + 1) * 4096 + c0;
    float* resg = sm + OFF_RES + s * 4096 + (g * 8) * 128;  // warp-private 8 rows
    float* hg   = sm + OFF_H   + s * 4096 + (g * 8) * 128;
    float* msb  = sm + OFF_MS;
    float* attv = sm + OFF_ATT;

    const int step = gridDim.x * 32;
    float2 pfv[8], upv[8];

#define PREFETCH(I0) do {                                                   \
    _Pragma("unroll")                                                       \
    for (int p = 0; p < 8; p++) {                                           \
        int i = (I0) + g * 8 + p; if (i >= n) i = n - 1;                    \
        int idx = g_ptidx[s][i];                                            \
        float inv = 1.0f / (float)g_counts[s][idx];                         \
        float2 sv = *(const float2*)&g_sums[s][(size_t)idx * 64 + c0];      \
        upv[p].x = sv.x * inv; upv[p].y = sv.y * inv;                       \
        pfv[p] = *(const float2*)&feats[(size_t)i * 64 + c0];               \
    }                                                                       \
} while (0)

#define GEMV(ABASE, WBASE) do {                                             \
    _Pragma("unroll") for (int p = 0; p < 8; p++) acc[p] = 0ull;            \
    _Pragma("unroll")                                                       \
    for (int k4 = 0; k4 < 16; k4++) {                                       \
        ull w0 = *(const ull*)((WBASE) + (4 * k4 + 0) * 64);                \
        ull w1 = *(const ull*)((WBASE) + (4 * k4 + 1) * 64);                \
        ull w2 = *(const ull*)((WBASE) + (4 * k4 + 2) * 64);                \
        ull w3 = *(const ull*)((WBASE) + (4 * k4 + 3) * 64);                \
        _Pragma("unroll")                                                   \
        for (int p = 0; p < 8; p++) {                                       \
            const float* row = (ABASE) + p * 128 + 8 * k4;                  \
            ulonglong2 aA = *(const ulonglong2*)row;                        \
            ulonglong2 aB = *(const ulonglong2*)(row + 4);                  \
            acc[p] = fma2(aA.x, w0, acc[p]);                                \
            acc[p] = fma2(aA.y, w1, acc[p]);                                \
            acc[p] = fma2(aB.x, w2, acc[p]);                                \
            acc[p] = fma2(aB.y, w3, acc[p]);                                \
        }                                                                   \
    }                                                                       \
} while (0)

    int i0 = blockIdx.x * 32;
    if (i0 < n) PREFETCH(i0);

    for (; i0 < n; i0 += step) {
        // ---- residual, duplicated store (warp-private buffer) ----
#pragma unroll
        for (int p = 0; p < 8; p++) {
            float r0 = pfv[p].x - upv[p].x;
            float r1 = pfv[p].y - upv[p].y;
            float4 d = make_float4(r0, r0, r1, r1);
            *(float4*)&resg[p * 128 + 4 * cp] = d;
        }
        __syncwarp();

        ull acc[8];
        // ---- GEMV1: h = relu(res @ W1 + b1) * feats ----
        GEMV(resg, w1base);
#pragma unroll
        for (int p = 0; p < 8; p++) {
            float2 u = unpack2(acc[p]);
            float h0 = fmaxf(u.x + b1c0, 0.0f) * pfv[p].x;
            float h1 = fmaxf(u.y + b1c1, 0.0f) * pfv[p].y;
            float4 d = make_float4(h0, h0, h1, h1);
            *(float4*)&hg[p * 128 + 4 * cp] = d;
        }
        __syncwarp();

        // ---- prefetch next tile's gather (hidden behind GEMV2) ----
        int inext = i0 + step;
        if (inext < n) PREFETCH(inext);

        // ---- GEMV2: ms = relu(h @ W2 + b2) ----
        GEMV(hg, w2base);
#pragma unroll
        for (int p = 0; p < 8; p++) {
            float2 u = unpack2(acc[p]);
            float m0 = fmaxf(u.x + b2c0, 0.0f);
            float m1 = fmaxf(u.y + b2c1, 0.0f);
            *(float2*)&msb[(s * 32 + g * 8 + p) * 64 + c0] = make_float2(m0, m1);
        }
        __syncthreads();  // S3: msb complete

        // ---- attention logits: logit[s] = sum_c ssum[c] * Wa[s][c] ----
        float pa[8];
#pragma unroll
        for (int p = 0; p < 8; p++) {
            int row = g * 8 + p;
            float2 m0 = *(const float2*)&msb[(0 * 32 + row) * 64 + c0];
            float2 m1 = *(const float2*)&msb[(1 * 32 + row) * 64 + c0];
            float2 m2 = *(const float2*)&msb[(2 * 32 + row) * 64 + c0];
            float ssx = m0.x + m1.x + m2.x;
            float ssy = m0.y + m1.y + m2.y;
            pa[p] = ssx * wac0 + ssy * wac1;
        }
#pragma unroll
        for (int off = 16; off; off >>= 1)
#pragma unroll
            for (int p = 0; p < 8; p++)
                pa[p] += __shfl_xor_sync(0xffffffffu, pa[p], off);
        if (cp == 0) {
#pragma unroll
            for (int p = 0; p < 8; p++)
                attv[s * 32 + g * 8 + p] = 1.0f / (1.0f + expf(-(pa[p] + bas)));
        }
        __syncthreads();  // S4: attv ready

        // ---- output: out = sum_s ms_s * att_s ----
#pragma unroll
        for (int u = 0; u < 3; u++) {
            int w = t + u * TPB5;
            if (w < 1024) {
                int p = w >> 5, cc = (w & 31) * 2;
                if (i0 + p < n) {
                    float a0 = attv[p], a1 = attv[32 + p], a2 = attv[64 + p];
                    float2 m0 = *(const float2*)&msb[p * 64 + cc];
                    float2 m1 = *(const float2*)&msb[(32 + p) * 64 + cc];
                    float2 m2 = *(const float2*)&msb[(64 + p) * 64 + cc];
                    float2 o;
                    o.x = m0.x * a0 + m1.x * a1 + m2.x * a2;
                    o.y = m0.y * a0 + m1.y * a1 + m2.y * a2;
                    *(float2*)&out[(size_t)(i0 + p) * 64 + cc] = o;
                }
            }
        }
        __syncthreads();  // S5: protect msb/attv WAR for next iteration
    }
#undef PREFETCH
#undef GEMV
}

// ---------------- host launcher ----------------
extern "C" void kernel_launch(void* const* d_in, const int* in_sizes, int n_in,
                              void* d_out, int out_size) {
    const float* feats = (const float*)d_in[0];
    const int*   coords = (const int*)d_in[1];
    const float* W1 = (const float*)d_in[2];
    const float* b1 = (const float*)d_in[3];
    const float* W2 = (const float*)d_in[4];
    const float* b2 = (const float*)d_in[5];
    const float* Wa = (const float*)d_in[6];
    const float* ba = (const float*)d_in[7];
    float* out = (float*)d_out;

    int n = in_sizes[1] / 4;   // coords is (N,4) int32
    if (n > NMAX) n = NMAX;

    k_clear<<<4096, 256>>>(n);
    dim3 gi((n + 255) / 256, 3);
    k_insert<<<gi, 256>>>(coords, n);
    dim3 ga((n * 16 + 255) / 256, 3);
    k_accum<<<ga, 256>>>(feats, n);
    k_select<<<gi, 256>>>(coords, n);

    int sms = 148;
    cudaDeviceGetAttribute(&sms, cudaDevAttrMultiProcessorCount, 0);
    cudaFuncSetAttribute(k_fuse, cudaFuncAttributeMaxDynamicSharedMemorySize, SMEM_BYTES);
    k_fuse<<<sms, TPB5, SMEM_BYTES>>>(feats, W1, b1, W2, b2, Wa, ba, out, n);
}

// round 5
// speedup vs baseline: 2.4081x; 1.4947x over previous
#include <cuda_runtime.h>
#include <cstdint>

#define NMAX   500000
#define HBITS  21
#define HSIZE  (1u << HBITS)
#define HMASK  (HSIZE - 1u)
#define EMPTYK 0xFFFFFFFFu
#define TPM    256

typedef unsigned long long ull;

// ---------------- device scratch ----------------
__device__ uint32_t g_keys[3][HSIZE];
__device__ int      g_vals[3][HSIZE];
__device__ int      g_counter[3];
__device__ int      g_pt2vox[3][NMAX];
__device__ float    g_sums[3][NMAX * 64];
__device__ int      g_counts[3][NMAX];
__device__ int      g_ptidx[3][NMAX];
__device__ float    g_ms[3][NMAX * 64];

__device__ __forceinline__ uint32_t hash32(uint32_t x) {
    x ^= x >> 16; x *= 0x85ebca6bu;
    x ^= x >> 13; x *= 0xc2b2ae35u;
    x ^= x >> 16;
    return x;
}

__device__ __forceinline__ ull fma2(ull a, ull b, ull c) {
    ull d;
    asm("fma.rn.f32x2 %0, %1, %2, %3;" : "=l"(d) : "l"(a), "l"(b), "l"(c));
    return d;
}
__device__ __forceinline__ float2 unpack2(ull v) {
    float2 r;
    asm("mov.b64 {%0, %1}, %2;" : "=f"(r.x), "=f"(r.y) : "l"(v));
    return r;
}

// ---------------- K1: clear all 3 hash tables + sums/counts ----------------
__global__ void k_clear(int n) {
    int tid = blockIdx.x * blockDim.x + threadIdx.x;
    int stride = gridDim.x * blockDim.x;
    int m4 = n * 16;
    float4 z = make_float4(0.f, 0.f, 0.f, 0.f);
#pragma unroll
    for (int s = 0; s < 3; s++) {
        float4* s4 = reinterpret_cast<float4*>(&g_sums[s][0]);
        for (int i = tid; i < m4; i += stride) s4[i] = z;
    }
    for (int i = tid; i < (int)HSIZE; i += stride) {
        g_keys[0][i] = EMPTYK; g_keys[1][i] = EMPTYK; g_keys[2][i] = EMPTYK;
        g_vals[0][i] = -1;     g_vals[1][i] = -1;     g_vals[2][i] = -1;
    }
    for (int i = tid; i < n; i += stride) {
        g_counts[0][i] = 0; g_counts[1][i] = 0; g_counts[2][i] = 0;
    }
    if (tid == 0) { g_counter[0] = 0; g_counter[1] = 0; g_counter[2] = 0; }
}

// ---------------- K2: hash-insert (all scales via blockIdx.y) ----------------
__global__ void k_insert(const int* __restrict__ coords, int n) {
    int i = blockIdx.x * blockDim.x + threadIdx.x;
    if (i >= n) return;
    int si = blockIdx.y;
    int shift = si + 1;
    int4 cd = reinterpret_cast<const int4*>(coords)[i];
    int vx = cd.x >> shift, vy = cd.y >> shift, vz = cd.z >> shift;
    uint32_t key = (uint32_t)((((cd.w * 512) + vx) * 512 + vy) * 512 + vz);
    uint32_t slot = hash32(key) & HMASK;
    int id = -1;
#pragma unroll 1
    while (true) {
        uint32_t old = atomicCAS(&g_keys[si][slot], EMPTYK, key);
        if (old == EMPTYK) {
            id = atomicAdd(&g_counter[si], 1);
            atomicExch(&g_vals[si][slot], id);
            break;
        }
        if (old == key) {
            volatile int* vp = (volatile int*)&g_vals[si][slot];
#pragma unroll 1
            while ((id = *vp) < 0) { __nanosleep(40); }
            break;
        }
        slot = (slot + 1) & HMASK;
    }
    g_pt2vox[si][i] = id;
    atomicAdd(&g_counts[si][id], 1);
}

// ---------------- K3: per-voxel feature sums ----------------
__global__ void k_accum(const float* __restrict__ feats, int n) {
    int tid = blockIdx.x * blockDim.x + threadIdx.x;
    if (tid >= n * 16) return;
    int si = blockIdx.y;
    int p = tid >> 4, q = tid & 15;
    float4 v = reinterpret_cast<const float4*>(feats)[tid];
    int vid = g_pt2vox[si][p];
    float* dst = &g_sums[si][(size_t)vid * 64 + q * 4];
    asm volatile("red.global.add.v4.f32 [%0], {%1, %2, %3, %4};"
                 :: "l"(dst), "f"(v.x), "f"(v.y), "f"(v.z), "f"(v.w)
                 : "memory");
}

// ---------------- K4: 8-corner probe + exact trilinear argmax ----------------
__device__ __forceinline__ int hlookup(int si, uint32_t key) {
    uint32_t slot = hash32(key) & HMASK;
#pragma unroll 1
    while (true) {
        uint32_t k = g_keys[si][slot];
        if (k == key) return g_vals[si][slot];
        if (k == EMPTYK) return -1;
        slot = (slot + 1) & HMASK;
    }
}

__global__ void k_select(const int* __restrict__ coords, int n) {
    int i = blockIdx.x * blockDim.x + threadIdx.x;
    if (i >= n) return;
    int si = blockIdx.y;
    int shift = si + 1;
    int4 cd = reinterpret_cast<const int4*>(coords)[i];
    int scale = 1 << shift;
    float invs = 1.0f / (float)scale;
    int vx = cd.x >> shift, vy = cd.y >> shift, vz = cd.z >> shift;
    float fx = (float)(cd.x - (vx << shift)) * invs;   // exact binary fractions
    float fy = (float)(cd.y - (vy << shift)) * invs;
    float fz = (float)(cd.z - (vz << shift)) * invs;
    float gx = 1.0f - fx, gy = 1.0f - fy, gz = 1.0f - fz;

    float bestw = -1.0f;
    int bestid = 0;
#pragma unroll
    for (int j = 0; j < 8; j++) {
        int bx = (j >> 2) & 1, by = (j >> 1) & 1, bz = j & 1;
        float w = (bx ? fx : gx) * (by ? fy : gy) * (bz ? fz : gz);  // exact
        uint32_t key = (uint32_t)((((cd.w * 512) + (vx + bx)) * 512 + (vy + by)) * 512 + (vz + bz));
        int id = hlookup(si, key);
        float val = (id >= 0) ? w : 0.0f;
        if (val > bestw) { bestw = val; bestid = id; }  // first-max == jnp.argmax
    }
    g_ptidx[si][i] = bestid;
}

// ---------------- K5: per-scale residual MLP (warp-independent) ----------------
// CTA: one scale (s = blockIdx.y), 8 warps, each warp processes 4 points per
// iteration, fully independent (no __syncthreads in the loop).
// Thread = lane cp owns channels {2cp, 2cp+1}.
// Weights packed per scale in smem as k-pairs: wpk[layer][cp][k2][j] =
//   (W[2k2][2cp+j], W[2k2+1][2cp+j]) packed in one ull.
//   Row stride 66 ull (pad 2) -> 16B aligned, conflict-free LDS.128.
// Activations natural layout (no duplication): fma2 accumulates
// (even-k, odd-k) partial sums per channel, horizontal add at the end.
#define WPK_ULL   (2 * 32 * 66)                    // 4224 ull = 33792 B
#define ACT_OFF_F (WPK_ULL * 2)                    // float index of act region
#define SMEM_MLP  (WPK_ULL * 8 + 8 * 512 * 4)     // 33792 + 16384 = 50176 B

__global__ __launch_bounds__(TPM, 4) void k_mlp(
    const float* __restrict__ feats,
    const float* __restrict__ W1g, const float* __restrict__ b1g,
    const float* __restrict__ W2g, const float* __restrict__ b2g,
    int n)
{
    extern __shared__ ull smu[];
    float* smf = (float*)smu;
    const int s    = blockIdx.y;
    const int bs   = blockIdx.x;
    const int nb   = gridDim.x;
    const int warp = threadIdx.x >> 5;
    const int lane = threadIdx.x & 31;
    const int c0   = lane * 2;

    // ---- stage + k-pair-pack this scale's weights ----
    for (int j = threadIdx.x; j < 8192; j += TPM) {
        int layer = j >> 12, r = j & 4095;
        int k = r >> 6, c = r & 63;
        float v = (layer ? W2g : W1g)[s * 4096 + r];
        smf[(((layer * 32 + (c >> 1)) * 66) + ((k >> 1) << 1) + (c & 1)) * 2 + (k & 1)] = v;
    }
    const float b1x = b1g[s * 64 + c0], b1y = b1g[s * 64 + c0 + 1];
    const float b2x = b2g[s * 64 + c0], b2y = b2g[s * 64 + c0 + 1];
    __syncthreads();

    const ull* w0b = smu + lane * 66;          // layer-1 weight row for this lane
    const ull* w1b = smu + 2112 + lane * 66;   // layer-2
    float* resw = smf + ACT_OFF_F + warp * 512;    // [4][64]
    float* hw   = resw + 256;                       // [4][64]

    const int tiles = (n + 3) >> 2;

#define GEMV(SRCF, WB) do {                                                    \
    _Pragma("unroll") for (int p = 0; p < 4; p++) { a0[p] = 0ull; a1[p] = 0ull; } \
    _Pragma("unroll")                                                          \
    for (int kc = 0; kc < 16; kc++) {                                          \
        ulonglong2 wA = *(const ulonglong2*)&(WB)[4 * kc];                     \
        ulonglong2 wB_ = *(const ulonglong2*)&(WB)[4 * kc + 2];                \
        _Pragma("unroll")                                                      \
        for (int p = 0; p < 4; p++) {                                          \
            ulonglong2 av = *(const ulonglong2*)&((const ull*)(SRCF))[p * 32 + 2 * kc]; \
            a0[p] = fma2(av.x, wA.x, a0[p]);                                   \
            a1[p] = fma2(av.x, wA.y, a1[p]);                                   \
            a0[p] = fma2(av.y, wB_.x, a0[p]);                                  \
            a1[p] = fma2(av.y, wB_.y, a1[p]);                                  \
        }                                                                      \
    }                                                                          \
} while (0)

    for (int t = bs * 8 + warp; t < tiles; t += nb * 8) {
        const int i0 = t * 4;
        float2 pf[4];

        // ---- gather voxel mean + residual (coalesced 256B rows) ----
#pragma unroll
        for (int p = 0; p < 4; p++) {
            int i = i0 + p; if (i >= n) i = n - 1;
            int idx = g_ptidx[s][i];
            float inv = 1.0f / (float)g_counts[s][idx];
            float2 sv = *(const float2*)&g_sums[s][(size_t)idx * 64 + c0];
            float2 f2 = *(const float2*)&feats[(size_t)i * 64 + c0];
            pf[p] = f2;
            *(float2*)&resw[p * 64 + c0] = make_float2(f2.x - sv.x * inv,
                                                       f2.y - sv.y * inv);
        }
        __syncwarp();

        ull a0[4], a1[4];
        // ---- GEMV1: h = relu(res @ W1 + b1) * feats ----
        GEMV(resw, w0b);
#pragma unroll
        for (int p = 0; p < 4; p++) {
            float2 u0 = unpack2(a0[p]);
            float2 u1 = unpack2(a1[p]);
            float h0 = fmaxf(u0.x + u0.y + b1x, 0.0f) * pf[p].x;
            float h1 = fmaxf(u1.x + u1.y + b1y, 0.0f) * pf[p].y;
            *(float2*)&hw[p * 64 + c0] = make_float2(h0, h1);
        }
        __syncwarp();

        // ---- GEMV2: ms = relu(h @ W2 + b2) ----
        GEMV(hw, w1b);
#pragma unroll
        for (int p = 0; p < 4; p++) {
            if (i0 + p < n) {
                float2 u0 = unpack2(a0[p]);
                float2 u1 = unpack2(a1[p]);
                float m0 = fmaxf(u0.x + u0.y + b2x, 0.0f);
                float m1 = fmaxf(u1.x + u1.y + b2y, 0.0f);
                *(float2*)&g_ms[s][(size_t)(i0 + p) * 64 + c0] = make_float2(m0, m1);
            }
        }
        __syncwarp();
    }
#undef GEMV
}

// ---------------- K6: attention + combine (streaming) ----------------
__global__ __launch_bounds__(256) void k_att(
    const float* __restrict__ Wag, const float* __restrict__ bag,
    float* __restrict__ out, int n)
{
    int warp = threadIdx.x >> 5, lane = threadIdx.x & 31;
    int i = blockIdx.x * 8 + warp;
    if (i >= n) return;
    int c0 = lane * 2;

    float2 m0 = *(const float2*)&g_ms[0][(size_t)i * 64 + c0];
    float2 m1 = *(const float2*)&g_ms[1][(size_t)i * 64 + c0];
    float2 m2 = *(const float2*)&g_ms[2][(size_t)i * 64 + c0];
    float ssx = m0.x + m1.x + m2.x;
    float ssy = m0.y + m1.y + m2.y;

    float2 wa0 = *(const float2*)&Wag[c0];
    float2 wa1 = *(const float2*)&Wag[64 + c0];
    float2 wa2 = *(const float2*)&Wag[128 + c0];
    float p0 = ssx * wa0.x + ssy * wa0.y;
    float p1 = ssx * wa1.x + ssy * wa1.y;
    float p2 = ssx * wa2.x + ssy * wa2.y;
#pragma unroll
    for (int off = 16; off; off >>= 1) {
        p0 += __shfl_xor_sync(0xffffffffu, p0, off);
        p1 += __shfl_xor_sync(0xffffffffu, p1, off);
        p2 += __shfl_xor_sync(0xffffffffu, p2, off);
    }
    float a0 = 1.0f / (1.0f + expf(-(p0 + bag[0])));
    float a1 = 1.0f / (1.0f + expf(-(p1 + bag[1])));
    float a2 = 1.0f / (1.0f + expf(-(p2 + bag[2])));

    float2 o;
    o.x = m0.x * a0 + m1.x * a1 + m2.x * a2;
    o.y = m0.y * a0 + m1.y * a1 + m2.y * a2;
    *(float2*)&out[(size_t)i * 64 + c0] = o;
}

// ---------------- host launcher ----------------
extern "C" void kernel_launch(void* const* d_in, const int* in_sizes, int n_in,
                              void* d_out, int out_size) {
    const float* feats = (const float*)d_in[0];
    const int*   coords = (const int*)d_in[1];
    const float* W1 = (const float*)d_in[2];
    const float* b1 = (const float*)d_in[3];
    const float* W2 = (const float*)d_in[4];
    const float* b2 = (const float*)d_in[5];
    const float* Wa = (const float*)d_in[6];
    const float* ba = (const float*)d_in[7];
    float* out = (float*)d_out;

    int n = in_sizes[1] / 4;   // coords is (N,4) int32
    if (n > NMAX) n = NMAX;

    k_clear<<<4096, 256>>>(n);
    dim3 gi((n + 255) / 256, 3);
    k_insert<<<gi, 256>>>(coords, n);
    dim3 ga((n * 16 + 255) / 256, 3);
    k_accum<<<ga, 256>>>(feats, n);
    k_select<<<gi, 256>>>(coords, n);

    int sms = 148;
    cudaDeviceGetAttribute(&sms, cudaDevAttrMultiProcessorCount, 0);
    cudaFuncSetAttribute(k_mlp, cudaFuncAttributeMaxDynamicSharedMemorySize, SMEM_MLP);
    dim3 gm(sms * 4, 3);   // 4 CTAs/SM per wave x 3 scales (3 waves), full occupancy
    k_mlp<<<gm, TPM, SMEM_MLP>>>(feats, W1, b1, W2, b2, n);

    k_att<<<(n + 7) / 8, 256>>>(Wa, ba, out, n);
}